// round 5
// baseline (speedup 1.0000x reference)
#include <cuda_runtime.h>
#include <cstdint>

#define Bb 8
#define Hh 4
#define Nn 2048
#define DM 256
#define DH 64

typedef unsigned long long u64;

// ---------------- scratch ---------------------------------------------------
__device__ float g_q [Bb*Hh*Nn*DH];
__device__ float g_kr[Bb*Hh*Nn*DH];
__device__ float g_v [Bb*Hh*Nn*DH];
__device__ float g_x [Bb*Nn*DM];

// ---------------- f32x2 helpers ---------------------------------------------
__device__ __forceinline__ u64 pack2(float lo, float hi){
    u64 r; asm("mov.b64 %0, {%1, %2};" : "=l"(r) : "f"(lo), "f"(hi)); return r;
}
__device__ __forceinline__ float2 unpack2(u64 v){
    float2 r; asm("mov.b64 {%0, %1}, %2;" : "=f"(r.x), "=f"(r.y) : "l"(v)); return r;
}
#define FMA2(d,a,b) asm("fma.rn.f32x2 %0, %1, %2, %0;" : "+l"(d) : "l"(a), "l"(b))

// exp2 on the FMA pipe (no MUFU). Input in log2 domain, |y| < 120.
__device__ __forceinline__ float exp2_fast(float y){
    y = fmaxf(y, -120.0f);
    float z = y + 12582912.0f;
    float f = y - (z - 12582912.0f);
    float p = 1.3333558146e-3f;
    p = fmaf(p, f, 9.6181291076e-3f);
    p = fmaf(p, f, 5.5504108664e-2f);
    p = fmaf(p, f, 2.4022650696e-1f);
    p = fmaf(p, f, 6.9314718056e-1f);
    p = fmaf(p, f, 1.0f);
    int zi = __float_as_int(z);
    float sc = __int_as_float((zi - 0x4B400000 + 127) << 23);
    return p * sc;
}

// ---------------- projection GEMM (dup-W inner loop) -------------------------
#define BM 128
#define BK 32

__global__ void __launch_bounds__(256) proj_kernel(
    const float* __restrict__ Q,  const float* __restrict__ K,
    const float* __restrict__ V,  const float* __restrict__ R,
    const float* __restrict__ Wq, const float* __restrict__ bq,
    const float* __restrict__ Wk, const float* __restrict__ bk,
    const float* __restrict__ Wv, const float* __restrict__ bv,
    const float* __restrict__ Wr, const float* __restrict__ br)
{
    __shared__ __align__(16) float As[BK][BM+4];
    __shared__ __align__(16) float Ws2[BK][128+4];   // duplicated cols
    const int tid = threadIdx.x;
    const int tx = tid & 15, ty = tid >> 4;
    const int m0 = blockIdx.x * BM;
    const int slot = blockIdx.y;
    const int head = slot & 3, which = slot >> 2;

    const float* A1 = (which == 0) ? Q : (which == 1) ? K : V;
    const float* W1 = (which == 0) ? Wq : (which == 1) ? Wk : Wv;
    const float* b1 = (which == 0) ? bq : (which == 1) ? bk : bv;
    const float* A2 = (which == 1) ? R  : nullptr;
    const float* W2 = (which == 1) ? Wr : nullptr;
    const float* b2 = (which == 1) ? br : nullptr;
    float* dst0 = (which == 0) ? g_q : (which == 1) ? g_kr : g_v;

    u64 acc[4][4];
#pragma unroll
    for (int i = 0; i < 4; i++)
#pragma unroll
        for (int j = 0; j < 4; j++) acc[i][j] = 0ull;

    const int nsrc = (A2 != nullptr) ? 2 : 1;
    for (int s = 0; s < nsrc; s++) {
        const float* A = s ? A2 : A1;
        const float* W = s ? W2 : W1;
        for (int kc = 0; kc < DM; kc += BK) {
            __syncthreads();
#pragma unroll
            for (int i = 0; i < 4; i++) {
                int idx = i * 256 + tid;
                int row = idx >> 3, kq = idx & 7;
                float4 v = *(const float4*)(A + (size_t)(m0 + row) * DM + kc + kq * 4);
                As[kq*4+0][row] = v.x; As[kq*4+1][row] = v.y;
                As[kq*4+2][row] = v.z; As[kq*4+3][row] = v.w;
            }
#pragma unroll
            for (int i = 0; i < 2; i++) {
                int idx = i * 256 + tid;
                int wk = idx >> 4, nq = idx & 15;
                float4 v = *(const float4*)(W + (size_t)head * (DM*DH) + (size_t)(kc + wk) * DH + nq * 4);
                *(float4*)&Ws2[wk][nq*8]   = make_float4(v.x, v.x, v.y, v.y);
                *(float4*)&Ws2[wk][nq*8+4] = make_float4(v.z, v.z, v.w, v.w);
            }
            __syncthreads();
#pragma unroll
            for (int kk = 0; kk < BK; kk++) {
                ulonglong2 a01 = *(const ulonglong2*)&As[kk][ty*8];
                ulonglong2 a23 = *(const ulonglong2*)&As[kk][ty*8+4];
                u64 av[4] = {a01.x, a01.y, a23.x, a23.y};
                ulonglong2 b01 = *(const ulonglong2*)&Ws2[kk][tx*8];
                ulonglong2 b23 = *(const ulonglong2*)&Ws2[kk][tx*8+4];
                u64 bb[4] = {b01.x, b01.y, b23.x, b23.y};
#pragma unroll
                for (int r = 0; r < 4; r++)
#pragma unroll
                    for (int c = 0; c < 4; c++)
                        FMA2(acc[r][c], av[r], bb[c]);
            }
        }
    }

    float4 bias = *(const float4*)(b1 + head * 64 + tx * 4);
    if (b2) {
        float4 t2 = *(const float4*)(b2 + head * 64 + tx * 4);
        bias.x += t2.x; bias.y += t2.y; bias.z += t2.z; bias.w += t2.w;
    }
#pragma unroll
    for (int r = 0; r < 4; r++) {
        float2 u0 = unpack2(acc[r][0]), u1 = unpack2(acc[r][1]);
        float2 u2 = unpack2(acc[r][2]), u3 = unpack2(acc[r][3]);
        float4 ev = make_float4(u0.x + bias.x, u1.x + bias.y, u2.x + bias.z, u3.x + bias.w);
        float4 ov = make_float4(u0.y + bias.x, u1.y + bias.y, u2.y + bias.z, u3.y + bias.w);
        int mrow = m0 + ty * 8 + r * 2;
        int bi = mrow >> 11, ni = mrow & (Nn - 1);
        *(float4*)(dst0 + (((size_t)bi * Hh + head) * Nn + ni) * DH + tx * 4) = ev;
        bi = (mrow + 1) >> 11; ni = (mrow + 1) & (Nn - 1);
        *(float4*)(dst0 + (((size_t)bi * Hh + head) * Nn + ni) * DH + tx * 4) = ov;
    }
}

__global__ void __launch_bounds__(256) outproj_kernel(
    const float* __restrict__ Wo, const float* __restrict__ bo,
    float* __restrict__ Cout)
{
    __shared__ __align__(16) float As[BK][BM+4];
    __shared__ __align__(16) float Ws2[BK][128+4];
    const int tid = threadIdx.x;
    const int tx = tid & 15, ty = tid >> 4;
    const int m0 = blockIdx.x * BM;
    const int nb = blockIdx.y;

    u64 acc[4][4];
#pragma unroll
    for (int i = 0; i < 4; i++)
#pragma unroll
        for (int j = 0; j < 4; j++) acc[i][j] = 0ull;

    for (int kc = 0; kc < DM; kc += BK) {
        __syncthreads();
#pragma unroll
        for (int i = 0; i < 4; i++) {
            int idx = i * 256 + tid;
            int row = idx >> 3, kq = idx & 7;
            float4 v = *(const float4*)(g_x + (size_t)(m0 + row) * DM + kc + kq * 4);
            As[kq*4+0][row] = v.x; As[kq*4+1][row] = v.y;
            As[kq*4+2][row] = v.z; As[kq*4+3][row] = v.w;
        }
#pragma unroll
        for (int i = 0; i < 2; i++) {
            int idx = i * 256 + tid;
            int n = idx >> 3, kq = idx & 7;
            float4 v = *(const float4*)(Wo + (size_t)(nb * 64 + n) * DM + kc + kq * 4);
            *(u64*)&Ws2[kq*4+0][2*n] = pack2(v.x, v.x);
            *(u64*)&Ws2[kq*4+1][2*n] = pack2(v.y, v.y);
            *(u64*)&Ws2[kq*4+2][2*n] = pack2(v.z, v.z);
            *(u64*)&Ws2[kq*4+3][2*n] = pack2(v.w, v.w);
        }
        __syncthreads();
#pragma unroll
        for (int kk = 0; kk < BK; kk++) {
            ulonglong2 a01 = *(const ulonglong2*)&As[kk][ty*8];
            ulonglong2 a23 = *(const ulonglong2*)&As[kk][ty*8+4];
            u64 av[4] = {a01.x, a01.y, a23.x, a23.y};
            ulonglong2 b01 = *(const ulonglong2*)&Ws2[kk][tx*8];
            ulonglong2 b23 = *(const ulonglong2*)&Ws2[kk][tx*8+4];
            u64 bb[4] = {b01.x, b01.y, b23.x, b23.y};
#pragma unroll
            for (int r = 0; r < 4; r++)
#pragma unroll
                for (int c = 0; c < 4; c++)
                    FMA2(acc[r][c], av[r], bb[c]);
        }
    }

    float4 bias = *(const float4*)(bo + nb * 64 + tx * 4);
#pragma unroll
    for (int r = 0; r < 4; r++) {
        float2 u0 = unpack2(acc[r][0]), u1 = unpack2(acc[r][1]);
        float2 u2 = unpack2(acc[r][2]), u3 = unpack2(acc[r][3]);
        float4 ev = make_float4(u0.x + bias.x, u1.x + bias.y, u2.x + bias.z, u3.x + bias.w);
        float4 ov = make_float4(u0.y + bias.x, u1.y + bias.y, u2.y + bias.z, u3.y + bias.w);
        int mrow = m0 + ty * 8 + r * 2;
        *(float4*)(Cout + (size_t)mrow * DM + nb * 64 + tx * 4) = ev;
        *(float4*)(Cout + (size_t)(mrow + 1) * DM + nb * 64 + tx * 4) = ov;
    }
}

// ---------------- fused attention v5: duplicated broadcast operands ----------
// Block 256 thr (16x16), tile 128 rows x 64 keys.
// Qs2[d][2*row]  : Q transposed, duplicated, pre-scaled   64 x 260
// Ks [d][key]    : K^T                                    64 x 68
// Vs [key][d]    : V natural                              64 x 68
// Ps2[row][2*key]: exp(S) duplicated                      128 x 132
#define QS2_OFF 0
#define KS_OFF  (64*260)
#define VS_OFF  (KS_OFF + 64*68)
#define PS2_OFF (VS_OFF + 64*68)
#define ATT_SMEM ((PS2_OFF + 128*132) * 4)

__global__ void __launch_bounds__(256, 1) attn_kernel(float* __restrict__ scores)
{
    extern __shared__ __align__(16) float sm[];
    float* Qs2 = sm + QS2_OFF;
    float* Ks  = sm + KS_OFF;
    float* Vs  = sm + VS_OFF;
    float* Ps2 = sm + PS2_OFF;

    const int tid = threadIdx.x;
    const int tx = tid & 15, ty = tid >> 4;
    const int b = blockIdx.z, h = blockIdx.y;
    const int q0 = blockIdx.x * 128;
    const size_t bh = (size_t)(b * Hh + h);
    const float* qb  = g_q  + (bh * Nn + q0) * DH;
    const float* krb = g_kr + bh * Nn * DH;
    const float* vb  = g_v  + bh * Nn * DH;
    float* sbase = scores + (bh * Nn + q0) * Nn;

    const float L2E = 1.4426950408889634f;

    // ---- Q: load once, transpose + duplicate + pre-scale by 1/8 ----
#pragma unroll
    for (int i = 0; i < 8; i++) {
        int fidx = i * 256 + tid;
        int qrow = fidx & 127, dg = fidx >> 7;
        float4 v = *(const float4*)(qb + (size_t)qrow * DH + dg * 4);
        *(u64*)&Qs2[(dg*4+0)*260 + 2*qrow] = pack2(v.x*0.125f, v.x*0.125f);
        *(u64*)&Qs2[(dg*4+1)*260 + 2*qrow] = pack2(v.y*0.125f, v.y*0.125f);
        *(u64*)&Qs2[(dg*4+2)*260 + 2*qrow] = pack2(v.z*0.125f, v.z*0.125f);
        *(u64*)&Qs2[(dg*4+3)*260 + 2*qrow] = pack2(v.w*0.125f, v.w*0.125f);
    }

    u64 oacc[8][2];
#pragma unroll
    for (int r = 0; r < 8; r++) { oacc[r][0] = 0ull; oacc[r][1] = 0ull; }
    float rowsum[8];
#pragma unroll
    for (int r = 0; r < 8; r++) rowsum[r] = 0.f;

    for (int kt = 0; kt < Nn; kt += 64) {
        __syncthreads();
        // K tile transposed; V tile natural
#pragma unroll
        for (int i = 0; i < 4; i++) {
            int fidx = i * 256 + tid;
            int key = fidx & 63, dg = fidx >> 6;
            float4 v = *(const float4*)(krb + (size_t)(kt + key) * DH + dg * 4);
            Ks[(dg*4+0)*68 + key] = v.x;
            Ks[(dg*4+1)*68 + key] = v.y;
            Ks[(dg*4+2)*68 + key] = v.z;
            Ks[(dg*4+3)*68 + key] = v.w;
        }
#pragma unroll
        for (int i = 0; i < 4; i++) {
            int fidx = i * 256 + tid;
            int key = fidx >> 4, dg = fidx & 15;
            *(float4*)&Vs[key*68 + dg*4] =
                *(const float4*)(vb + (size_t)(kt + key) * DH + dg * 4);
        }
        __syncthreads();

        // ---- Phase 1: S = Q K^T ----
        u64 sacc[8][2];
#pragma unroll
        for (int r = 0; r < 8; r++) { sacc[r][0] = 0ull; sacc[r][1] = 0ull; }
#pragma unroll 16
        for (int d = 0; d < DH; d++) {
            const float* qrow = &Qs2[d*260 + 2*(ty*8)];
            ulonglong2 qA = *(const ulonglong2*)(qrow);
            ulonglong2 qB = *(const ulonglong2*)(qrow + 4);
            ulonglong2 qC = *(const ulonglong2*)(qrow + 8);
            ulonglong2 qD = *(const ulonglong2*)(qrow + 12);
            ulonglong2 kk = *(const ulonglong2*)&Ks[d*68 + tx*4];
            FMA2(sacc[0][0], qA.x, kk.x); FMA2(sacc[0][1], qA.x, kk.y);
            FMA2(sacc[1][0], qA.y, kk.x); FMA2(sacc[1][1], qA.y, kk.y);
            FMA2(sacc[2][0], qB.x, kk.x); FMA2(sacc[2][1], qB.x, kk.y);
            FMA2(sacc[3][0], qB.y, kk.x); FMA2(sacc[3][1], qB.y, kk.y);
            FMA2(sacc[4][0], qC.x, kk.x); FMA2(sacc[4][1], qC.x, kk.y);
            FMA2(sacc[5][0], qC.y, kk.x); FMA2(sacc[5][1], qC.y, kk.y);
            FMA2(sacc[6][0], qD.x, kk.x); FMA2(sacc[6][1], qD.x, kk.y);
            FMA2(sacc[7][0], qD.y, kk.x); FMA2(sacc[7][1], qD.y, kk.y);
        }

        // ---- softmax: scores out, exp -> Ps2 (duplicated), rowsum ----
#pragma unroll
        for (int r = 0; r < 8; r++) {
            float2 s01 = unpack2(sacc[r][0]);
            float2 s23 = unpack2(sacc[r][1]);
            int row = ty * 8 + r;
            *(float4*)(sbase + (size_t)row * Nn + kt + tx * 4) =
                make_float4(s01.x, s01.y, s23.x, s23.y);
            float p0 = exp2_fast(s01.x * L2E);
            float p1 = exp2_fast(s01.y * L2E);
            float p2 = exp2_fast(s23.x * L2E);
            float p3 = exp2_fast(s23.y * L2E);
            rowsum[r] += (p0 + p1) + (p2 + p3);
            *(float4*)&Ps2[row*132 + 8*tx]     = make_float4(p0, p0, p1, p1);
            *(float4*)&Ps2[row*132 + 8*tx + 4] = make_float4(p2, p2, p3, p3);
        }
        __syncthreads();

        // ---- Phase 2: O += P V  (key pairs) ----
#pragma unroll 8
        for (int kp = 0; kp < 32; kp++) {
            ulonglong2 v0 = *(const ulonglong2*)&Vs[(2*kp)*68 + tx*4];
            ulonglong2 v1 = *(const ulonglong2*)&Vs[(2*kp+1)*68 + tx*4];
#pragma unroll
            for (int r = 0; r < 8; r++) {
                ulonglong2 pp = *(const ulonglong2*)&Ps2[(ty*8+r)*132 + 4*kp];
                FMA2(oacc[r][0], pp.x, v0.x); FMA2(oacc[r][1], pp.x, v0.y);
                FMA2(oacc[r][0], pp.y, v1.x); FMA2(oacc[r][1], pp.y, v1.y);
            }
        }
    }

    // ---- rowsum reduction across tx (Ps2 as scratch) ----
    __syncthreads();
#pragma unroll
    for (int r = 0; r < 8; r++) Ps2[(ty*8+r)*132 + tx] = rowsum[r];
    __syncthreads();

#pragma unroll
    for (int r = 0; r < 8; r++) {
        int row = ty * 8 + r;
        float tot = 0.f;
#pragma unroll
        for (int t = 0; t < 16; t++) tot += Ps2[row*132 + t];
        float inv = 1.0f / tot;
        float2 d01 = unpack2(oacc[r][0]);
        float2 d23 = unpack2(oacc[r][1]);
        *(float4*)(g_x + ((size_t)b * Nn + q0 + row) * DM + h * DH + tx * 4) =
            make_float4(d01.x * inv, d01.y * inv, d23.x * inv, d23.y * inv);
    }
}

// ---------------- launch -----------------------------------------------------
extern "C" void kernel_launch(void* const* d_in, const int* in_sizes, int n_in,
                              void* d_out, int out_size)
{
    (void)in_sizes; (void)n_in; (void)out_size;
    const float* Q  = (const float*)d_in[0];
    const float* K  = (const float*)d_in[1];
    const float* V  = (const float*)d_in[2];
    const float* R  = (const float*)d_in[3];
    const float* Wq = (const float*)d_in[4];
    const float* bq = (const float*)d_in[5];
    const float* Wk = (const float*)d_in[6];
    const float* bk = (const float*)d_in[7];
    const float* Wv = (const float*)d_in[8];
    const float* bv = (const float*)d_in[9];
    const float* Wr = (const float*)d_in[10];
    const float* br = (const float*)d_in[11];
    const float* Wo = (const float*)d_in[12];
    const float* bo = (const float*)d_in[13];

    float* outp   = (float*)d_out;
    float* scores = outp + (size_t)Bb * Nn * DM;

    dim3 gp(Nn * Bb / BM, 12);
    proj_kernel<<<gp, 256>>>(Q, K, V, R, Wq, bq, Wk, bk, Wv, bv, Wr, br);

    cudaFuncSetAttribute(attn_kernel, cudaFuncAttributeMaxDynamicSharedMemorySize, ATT_SMEM);
    dim3 ga(Nn / 128, Hh, Bb);
    attn_kernel<<<ga, 256, ATT_SMEM>>>(scores);

    dim3 go(Nn * Bb / BM, 4);
    outproj_kernel<<<go, 256>>>(Wo, bo, outp);
}